// round 10
// baseline (speedup 1.0000x reference)
#include <cuda_runtime.h>
#include <cstdint>

#define D 128
#define N_MAX 50064
#define E_MAX 500000
#define FB 160          // fill blocks appended to kernel A

// ---- device scratch (no allocations; .bss zero at load, kernels self-clean) ----
__device__ float g_h[(size_t)N_MAX * D];   // h' = dis[r] * (x @ W)[r]
__device__ int   g_cnt[N_MAX];             // in-degree (excl. self); zeroed by k_final
__device__ float g_dis[N_MAX];             // rsqrt(1 + cnt)
__device__ int   g_start[N_MAX];
__device__ int   g_cursor[N_MAX];
__device__ int   g_adj[E_MAX];
__device__ int   g_total;                  // ticket; zeroed by k_final
__device__ float g_colstats[2 * D];        // zeroed by k_count

// ---------------------------------------------------------------------------
// K1: in-degree count (grid-stride); block 0 zeros column stats
// ---------------------------------------------------------------------------
__global__ void k_count(const int* __restrict__ pos, int E) {
    if (blockIdx.x == 0) g_colstats[threadIdx.x] = 0.0f;   // 256 == 2*D
    for (int e = blockIdx.x * 256 + threadIdx.x; e < E; e += gridDim.x * 256)
        atomicAdd(&g_cnt[pos[(size_t)E + e]], 1);
}

// ---------------------------------------------------------------------------
// K2: segment allocation — block scan + one atomic ticket; dis; cursor
// ---------------------------------------------------------------------------
__global__ void k_alloc(int N) {
    __shared__ int sh[256];
    __shared__ int base;
    int t = threadIdx.x;
    int i = blockIdx.x * 256 + t;
    int c = (i < N) ? g_cnt[i] : 0;
    sh[t] = c;
    __syncthreads();
    for (int off = 1; off < 256; off <<= 1) {
        int v = (t >= off) ? sh[t - off] : 0;
        __syncthreads();
        sh[t] += v;
        __syncthreads();
    }
    if (t == 255) base = atomicAdd(&g_total, sh[255]);
    __syncthreads();
    if (i < N) {
        int start = base + sh[t] - c;
        g_start[i]  = start;
        g_cursor[i] = start;
        g_dis[i]    = rsqrtf(1.0f + (float)c);
    }
}

// ---------------------------------------------------------------------------
// Kernel A (block-specialized):
//   blocks [0, GB)     : h' = dis[r] * (x @ W)  (fp32x2 GEMM, 128x128 tile,
//                        register-double-buffered tile loads)
//   blocks [GB, GB+FB) : CSC adjacency fill (independent of h)
// ---------------------------------------------------------------------------
#define FMA2(acc, a, b) asm("fma.rn.f32x2 %0, %1, %2, %0;" : "+l"(acc) : "l"(a), "l"(b))

__global__ void __launch_bounds__(256) kA(const float* __restrict__ x,
                                          const float* __restrict__ W,
                                          const int* __restrict__ pos,
                                          int N, int E, int GB) {
    if (blockIdx.x >= GB) {
        // ---- fill path ----
        int b = blockIdx.x - GB;
        for (int e = b * 256 + threadIdx.x; e < E; e += FB * 256) {
            int col = pos[(size_t)E + e];
            int p = atomicAdd(&g_cursor[col], 1);
            g_adj[p] = pos[e];
        }
        return;
    }

    // ---- GEMM path ----
    __shared__ float xs[16][128];   // transposed x tile
    __shared__ float ws[16][128];   // W tile

    const int t  = threadIdx.x;
    const int r0 = blockIdx.x * 128;
    const int cg = t & 15;
    const int rg = t >> 4;

    // per-thread load coordinates (fixed across k-steps)
    const int lrowA = t >> 2;               // x tile u=0: row 0..63
    const int lkqA  = (t & 3) * 4;
    const int lrowB = (t + 256) >> 2;       // x tile u=1: row 64..127
    const int lkqB  = lkqA;
    const int wkkA  = t >> 5;               // W tile u=0: kk 0..7
    const int wc4A  = (t & 31) * 4;
    const int wkkB  = (t + 256) >> 5;       // W tile u=1: kk 8..15
    const int wc4B  = wc4A;

    const bool okA = (r0 + lrowA) < N;
    const bool okB = (r0 + lrowB) < N;

    float4 rxA, rxB, rwA, rwB;              // prefetch registers

    // prologue: load k0 = 0
    rxA = okA ? *(const float4*)(x + (size_t)(r0 + lrowA) * D + lkqA)
              : make_float4(0.f, 0.f, 0.f, 0.f);
    rxB = okB ? *(const float4*)(x + (size_t)(r0 + lrowB) * D + lkqB)
              : make_float4(0.f, 0.f, 0.f, 0.f);
    rwA = *(const float4*)(W + (size_t)wkkA * D + wc4A);
    rwB = *(const float4*)(W + (size_t)wkkB * D + wc4B);

    unsigned long long acc[8][4];
#pragma unroll
    for (int i = 0; i < 8; i++)
#pragma unroll
        for (int j = 0; j < 4; j++) acc[i][j] = 0ull;

#pragma unroll
    for (int k0 = 0; k0 < D; k0 += 16) {
        // stage current regs -> smem
        xs[lkqA + 0][lrowA] = rxA.x;
        xs[lkqA + 1][lrowA] = rxA.y;
        xs[lkqA + 2][lrowA] = rxA.z;
        xs[lkqA + 3][lrowA] = rxA.w;
        xs[lkqB + 0][lrowB] = rxB.x;
        xs[lkqB + 1][lrowB] = rxB.y;
        xs[lkqB + 2][lrowB] = rxB.z;
        xs[lkqB + 3][lrowB] = rxB.w;
        *(float4*)&ws[wkkA][wc4A] = rwA;
        *(float4*)&ws[wkkB][wc4B] = rwB;
        __syncthreads();

        // prefetch next tile while computing this one
        int kn = k0 + 16;
        if (kn < D) {
            rxA = okA ? *(const float4*)(x + (size_t)(r0 + lrowA) * D + kn + lkqA)
                      : make_float4(0.f, 0.f, 0.f, 0.f);
            rxB = okB ? *(const float4*)(x + (size_t)(r0 + lrowB) * D + kn + lkqB)
                      : make_float4(0.f, 0.f, 0.f, 0.f);
            rwA = *(const float4*)(W + (size_t)(kn + wkkA) * D + wc4A);
            rwB = *(const float4*)(W + (size_t)(kn + wkkB) * D + wc4B);
        }

#pragma unroll
        for (int kk = 0; kk < 16; kk++) {
            ulonglong2 wA = *(const ulonglong2*)&ws[kk][cg * 8];
            ulonglong2 wB = *(const ulonglong2*)&ws[kk][cg * 8 + 4];
            float4 xa = *(const float4*)&xs[kk][rg * 8];
            float4 xb = *(const float4*)&xs[kk][rg * 8 + 4];
            float xv[8] = {xa.x, xa.y, xa.z, xa.w, xb.x, xb.y, xb.z, xb.w};
#pragma unroll
            for (int i = 0; i < 8; i++) {
                unsigned long long xd;
                asm("mov.b64 %0, {%1, %1};" : "=l"(xd) : "f"(xv[i]));
                FMA2(acc[i][0], xd, wA.x);
                FMA2(acc[i][1], xd, wA.y);
                FMA2(acc[i][2], xd, wB.x);
                FMA2(acc[i][3], xd, wB.y);
            }
        }
        __syncthreads();
    }

#pragma unroll
    for (int i = 0; i < 8; i++) {
        int gr = r0 + rg * 8 + i;
        if (gr < N) {
            float s = g_dis[gr];
            float2 p0 = *(float2*)&acc[i][0];
            float2 p1 = *(float2*)&acc[i][1];
            float2 p2 = *(float2*)&acc[i][2];
            float2 p3 = *(float2*)&acc[i][3];
            *(float4*)(g_h + (size_t)gr * D + cg * 8) =
                make_float4(p0.x * s, p0.y * s, p1.x * s, p1.y * s);
            *(float4*)(g_h + (size_t)gr * D + cg * 8 + 4) =
                make_float4(p2.x * s, p2.y * s, p3.x * s, p3.y * s);
        }
    }
}

// ---------------------------------------------------------------------------
// K3: gather — one node per warp, pure v4 adds (R6 form), fused column stats.
//     out[c] = dis[c] * (h'[c] + sum_in h'[r])
// ---------------------------------------------------------------------------
__global__ void __launch_bounds__(256) k_gather(float* __restrict__ out, int N) {
    __shared__ float ssum[8][128];
    __shared__ float ssq[8][128];
    int lane = threadIdx.x & 31;
    int w    = threadIdx.x >> 5;

    float4 cs = make_float4(0.f, 0.f, 0.f, 0.f);
    float4 cq = make_float4(0.f, 0.f, 0.f, 0.f);

    for (int node = blockIdx.x * 8 + w; node < N; node += gridDim.x * 8) {
        int start = g_start[node];
        int cnt   = g_cnt[node];

        float4 acc = *(const float4*)(g_h + (size_t)node * D + lane * 4);  // self

        for (int j = 0; j < cnt; j += 32) {
            int m = min(32, cnt - j);
            int idx = (lane < m) ? g_adj[start + j + lane] : 0;
            int k = 0;
            for (; k + 4 <= m; k += 4) {     // 4-deep MLP, pure adds
                int rA = __shfl_sync(0xffffffffu, idx, k + 0);
                int rB = __shfl_sync(0xffffffffu, idx, k + 1);
                int rC = __shfl_sync(0xffffffffu, idx, k + 2);
                int rD = __shfl_sync(0xffffffffu, idx, k + 3);
                float4 vA = *(const float4*)(g_h + (size_t)rA * D + lane * 4);
                float4 vB = *(const float4*)(g_h + (size_t)rB * D + lane * 4);
                float4 vC = *(const float4*)(g_h + (size_t)rC * D + lane * 4);
                float4 vD = *(const float4*)(g_h + (size_t)rD * D + lane * 4);
                acc.x += vA.x + vB.x + vC.x + vD.x;
                acc.y += vA.y + vB.y + vC.y + vD.y;
                acc.z += vA.z + vB.z + vC.z + vD.z;
                acc.w += vA.w + vB.w + vC.w + vD.w;
            }
            for (; k < m; k++) {
                int r = __shfl_sync(0xffffffffu, idx, k);
                float4 v = *(const float4*)(g_h + (size_t)r * D + lane * 4);
                acc.x += v.x; acc.y += v.y; acc.z += v.z; acc.w += v.w;
            }
        }

        float s = g_dis[node];
        float4 o = make_float4(acc.x * s, acc.y * s, acc.z * s, acc.w * s);
        *(float4*)(out + (size_t)node * D + lane * 4) = o;
        cs.x += o.x; cs.y += o.y; cs.z += o.z; cs.w += o.w;
        cq.x += o.x * o.x; cq.y += o.y * o.y;
        cq.z += o.z * o.z; cq.w += o.w * o.w;
    }

    *(float4*)&ssum[w][lane * 4] = cs;
    *(float4*)&ssq[w][lane * 4]  = cq;
    __syncthreads();
    int t = threadIdx.x;
    if (t < D) {
        float a = 0.f, b = 0.f;
#pragma unroll
        for (int w2 = 0; w2 < 8; w2++) { a += ssum[w2][t]; b += ssq[w2][t]; }
        atomicAdd(&g_colstats[t], a);
        atomicAdd(&g_colstats[D + t], b);
    }
}

// ---------------------------------------------------------------------------
// K4: BN (training mode, biased var) + ReLU in place; self-clean cnt/total
// ---------------------------------------------------------------------------
__global__ void k_final(const float* __restrict__ gamma,
                        const float* __restrict__ beta,
                        float* __restrict__ out, int N) {
    __shared__ float sscale[D], sshift[D];
    int t = threadIdx.x;
    if (t < D) {
        float invN = 1.0f / (float)N;
        float mean = g_colstats[t] * invN;
        float var  = g_colstats[D + t] * invN - mean * mean;
        float inv  = rsqrtf(var + 1e-5f);
        float sc   = gamma[t] * inv;
        sscale[t]  = sc;
        sshift[t]  = beta[t] - mean * sc;
    }
    __syncthreads();

    int gid = blockIdx.x * blockDim.x + t;
    if (gid < N) g_cnt[gid] = 0;
    if (gid == 0) g_total = 0;

    size_t total4 = (size_t)N * (D / 4);
    size_t stride = (size_t)gridDim.x * blockDim.x;
    for (size_t i = (size_t)blockIdx.x * blockDim.x + t; i < total4; i += stride) {
        int c = (int)(i & 31) * 4;
        float4 v = ((float4*)out)[i];
        v.x = fmaxf(v.x * sscale[c + 0] + sshift[c + 0], 0.0f);
        v.y = fmaxf(v.y * sscale[c + 1] + sshift[c + 1], 0.0f);
        v.z = fmaxf(v.z * sscale[c + 2] + sshift[c + 2], 0.0f);
        v.w = fmaxf(v.w * sscale[c + 3] + sshift[c + 3], 0.0f);
        ((float4*)out)[i] = v;
    }
}

// ---------------------------------------------------------------------------
extern "C" void kernel_launch(void* const* d_in, const int* in_sizes, int n_in,
                              void* d_out, int out_size) {
    const float* x     = (const float*)d_in[0];
    const int*   pos   = (const int*)d_in[1];   // int32 (JAX canonicalizes int64)
    // d_in[2] = neg_edge_index: weight 0 => no-op, skipped
    const float* W     = (const float*)d_in[3];
    // d_in[4] = b: cancels exactly inside BatchNorm, skipped
    const float* gamma = (const float*)d_in[5];
    const float* beta  = (const float*)d_in[6];
    float*       out   = (float*)d_out;

    const int N  = in_sizes[0] / D;
    const int E  = in_sizes[1] / 2;
    const int GB = (N + 127) / 128;

    k_count <<<256, 256>>>(pos, E);
    k_alloc <<<(N + 255) / 256, 256>>>(N);
    kA      <<<GB + FB, 256>>>(x, W, pos, N, E, GB);
    k_gather<<<888, 256>>>(out, N);     // 148 SMs x 6 blocks
    k_final <<<784, 256>>>(gamma, beta, out, N);
}

// round 11
// speedup vs baseline: 1.0622x; 1.0622x over previous
#include <cuda_runtime.h>
#include <cstdint>

#define D 128
#define N_MAX 50064
#define E_MAX 500000
#define FB 160          // fill blocks appended to kernel A
#define GATHER_BLOCKS 888   // 148 SMs x 6 blocks — must ALL be co-resident

// ---- device scratch (no allocations; .bss zero at load, kernels self-clean) ----
__device__ float g_h[(size_t)N_MAX * D];   // h' = dis[r] * (x @ W)[r]
__device__ int   g_cnt[N_MAX];             // in-degree (excl. self); zeroed by gather BN phase
__device__ float g_dis[N_MAX];             // rsqrt(1 + cnt)
__device__ int   g_start[N_MAX];
__device__ int   g_cursor[N_MAX];
__device__ int   g_adj[E_MAX];
__device__ int   g_total;                  // ticket; zeroed by gather BN phase
__device__ int   g_arrive;                 // grid barrier; zeroed by k_alloc
__device__ float g_colstats[2 * D];        // zeroed by k_count

// ---------------------------------------------------------------------------
// K1: in-degree count (grid-stride); block 0 zeros column stats
// ---------------------------------------------------------------------------
__global__ void k_count(const int* __restrict__ pos, int E) {
    if (blockIdx.x == 0) g_colstats[threadIdx.x] = 0.0f;   // 256 == 2*D
    for (int e = blockIdx.x * 256 + threadIdx.x; e < E; e += gridDim.x * 256)
        atomicAdd(&g_cnt[pos[(size_t)E + e]], 1);
}

// ---------------------------------------------------------------------------
// K2: segment allocation — block scan + one atomic ticket; dis; cursor
// ---------------------------------------------------------------------------
__global__ void k_alloc(int N) {
    __shared__ int sh[256];
    __shared__ int base;
    int t = threadIdx.x;
    int i = blockIdx.x * 256 + t;
    if (i == 0) g_arrive = 0;              // reset grid barrier (stream-ordered)
    int c = (i < N) ? g_cnt[i] : 0;
    sh[t] = c;
    __syncthreads();
    for (int off = 1; off < 256; off <<= 1) {
        int v = (t >= off) ? sh[t - off] : 0;
        __syncthreads();
        sh[t] += v;
        __syncthreads();
    }
    if (t == 255) base = atomicAdd(&g_total, sh[255]);
    __syncthreads();
    if (i < N) {
        int start = base + sh[t] - c;
        g_start[i]  = start;
        g_cursor[i] = start;
        g_dis[i]    = rsqrtf(1.0f + (float)c);
    }
}

// ---------------------------------------------------------------------------
// Kernel A (block-specialized):
//   blocks [0, GB)     : h' = dis[r] * (x @ W)  (fp32x2 GEMM, 128x128 tile)
//   blocks [GB, GB+FB) : CSC adjacency fill (independent of h)
// ---------------------------------------------------------------------------
#define FMA2(acc, a, b) asm("fma.rn.f32x2 %0, %1, %2, %0;" : "+l"(acc) : "l"(a), "l"(b))

__global__ void __launch_bounds__(256) kA(const float* __restrict__ x,
                                          const float* __restrict__ W,
                                          const int* __restrict__ pos,
                                          int N, int E, int GB) {
    if (blockIdx.x >= GB) {
        // ---- fill path ----
        int b = blockIdx.x - GB;
        for (int e = b * 256 + threadIdx.x; e < E; e += FB * 256) {
            int col = pos[(size_t)E + e];
            int p = atomicAdd(&g_cursor[col], 1);
            g_adj[p] = pos[e];
        }
        return;
    }

    // ---- GEMM path ----
    __shared__ float xs[16][128];   // transposed x tile
    __shared__ float ws[16][128];   // W tile

    const int t  = threadIdx.x;
    const int r0 = blockIdx.x * 128;
    const int cg = t & 15;
    const int rg = t >> 4;

    unsigned long long acc[8][4];
#pragma unroll
    for (int i = 0; i < 8; i++)
#pragma unroll
        for (int j = 0; j < 4; j++) acc[i][j] = 0ull;

    for (int k0 = 0; k0 < D; k0 += 16) {
        __syncthreads();
#pragma unroll
        for (int u = 0; u < 2; u++) {
            int id  = t + u * 256;
            int row = id >> 2;
            int kq  = (id & 3) * 4;
            float4 v = make_float4(0.f, 0.f, 0.f, 0.f);
            int gr = r0 + row;
            if (gr < N) v = *(const float4*)(x + (size_t)gr * D + k0 + kq);
            xs[kq + 0][row] = v.x;
            xs[kq + 1][row] = v.y;
            xs[kq + 2][row] = v.z;
            xs[kq + 3][row] = v.w;
        }
#pragma unroll
        for (int u = 0; u < 2; u++) {
            int id = t + u * 256;
            int kk = id >> 5;
            int c4 = id & 31;
            *(float4*)&ws[kk][c4 * 4] =
                *(const float4*)(W + (size_t)(k0 + kk) * D + c4 * 4);
        }
        __syncthreads();

#pragma unroll
        for (int kk = 0; kk < 16; kk++) {
            ulonglong2 wA = *(const ulonglong2*)&ws[kk][cg * 8];
            ulonglong2 wB = *(const ulonglong2*)&ws[kk][cg * 8 + 4];
            float4 xa = *(const float4*)&xs[kk][rg * 8];
            float4 xb = *(const float4*)&xs[kk][rg * 8 + 4];
            float xv[8] = {xa.x, xa.y, xa.z, xa.w, xb.x, xb.y, xb.z, xb.w};
#pragma unroll
            for (int i = 0; i < 8; i++) {
                unsigned long long xd;
                asm("mov.b64 %0, {%1, %1};" : "=l"(xd) : "f"(xv[i]));
                FMA2(acc[i][0], xd, wA.x);
                FMA2(acc[i][1], xd, wA.y);
                FMA2(acc[i][2], xd, wB.x);
                FMA2(acc[i][3], xd, wB.y);
            }
        }
    }

#pragma unroll
    for (int i = 0; i < 8; i++) {
        int gr = r0 + rg * 8 + i;
        if (gr < N) {
            float s = g_dis[gr];
            float2 p0 = *(float2*)&acc[i][0];
            float2 p1 = *(float2*)&acc[i][1];
            float2 p2 = *(float2*)&acc[i][2];
            float2 p3 = *(float2*)&acc[i][3];
            *(float4*)(g_h + (size_t)gr * D + cg * 8) =
                make_float4(p0.x * s, p0.y * s, p1.x * s, p1.y * s);
            *(float4*)(g_h + (size_t)gr * D + cg * 8 + 4) =
                make_float4(p2.x * s, p2.y * s, p3.x * s, p3.y * s);
        }
    }
}

// ---------------------------------------------------------------------------
// K3: gather + column stats + grid barrier + fused BN/ReLU.
//     Phase 1: out[c] = dis[c]*(h'[c] + sum_in h'[r]); accumulate stats.
//     Barrier: all 888 blocks co-resident (39 regs, 8KB smem) -> safe spin.
//     Phase 2: out = relu(gamma*xhat + beta) in place; self-clean cnt/total.
// ---------------------------------------------------------------------------
__global__ void __launch_bounds__(256, 6) k_gather(float* __restrict__ out,
                                                   const float* __restrict__ gamma,
                                                   const float* __restrict__ beta,
                                                   int N) {
    __shared__ float ssum[8][128];
    __shared__ float ssq[8][128];
    int lane = threadIdx.x & 31;
    int w    = threadIdx.x >> 5;

    float4 cs = make_float4(0.f, 0.f, 0.f, 0.f);
    float4 cq = make_float4(0.f, 0.f, 0.f, 0.f);

    for (int node = blockIdx.x * 8 + w; node < N; node += gridDim.x * 8) {
        int start = g_start[node];
        int cnt   = g_cnt[node];

        float4 acc = *(const float4*)(g_h + (size_t)node * D + lane * 4);  // self

        for (int j = 0; j < cnt; j += 32) {
            int m = min(32, cnt - j);
            int idx = (lane < m) ? g_adj[start + j + lane] : 0;
            int k = 0;
            for (; k + 4 <= m; k += 4) {     // 4-deep MLP, pure adds
                int rA = __shfl_sync(0xffffffffu, idx, k + 0);
                int rB = __shfl_sync(0xffffffffu, idx, k + 1);
                int rC = __shfl_sync(0xffffffffu, idx, k + 2);
                int rD = __shfl_sync(0xffffffffu, idx, k + 3);
                float4 vA = *(const float4*)(g_h + (size_t)rA * D + lane * 4);
                float4 vB = *(const float4*)(g_h + (size_t)rB * D + lane * 4);
                float4 vC = *(const float4*)(g_h + (size_t)rC * D + lane * 4);
                float4 vD = *(const float4*)(g_h + (size_t)rD * D + lane * 4);
                acc.x += vA.x + vB.x + vC.x + vD.x;
                acc.y += vA.y + vB.y + vC.y + vD.y;
                acc.z += vA.z + vB.z + vC.z + vD.z;
                acc.w += vA.w + vB.w + vC.w + vD.w;
            }
            for (; k < m; k++) {
                int r = __shfl_sync(0xffffffffu, idx, k);
                float4 v = *(const float4*)(g_h + (size_t)r * D + lane * 4);
                acc.x += v.x; acc.y += v.y; acc.z += v.z; acc.w += v.w;
            }
        }

        float s = g_dis[node];
        float4 o = make_float4(acc.x * s, acc.y * s, acc.z * s, acc.w * s);
        *(float4*)(out + (size_t)node * D + lane * 4) = o;
        cs.x += o.x; cs.y += o.y; cs.z += o.z; cs.w += o.w;
        cq.x += o.x * o.x; cq.y += o.y * o.y;
        cq.z += o.z * o.z; cq.w += o.w * o.w;
    }

    *(float4*)&ssum[w][lane * 4] = cs;
    *(float4*)&ssq[w][lane * 4]  = cq;
    __syncthreads();
    {
        int t = threadIdx.x;
        if (t < D) {
            float a = 0.f, b = 0.f;
#pragma unroll
            for (int w2 = 0; w2 < 8; w2++) { a += ssum[w2][t]; b += ssq[w2][t]; }
            atomicAdd(&g_colstats[t], a);
            atomicAdd(&g_colstats[D + t], b);
        }
    }

    // ---- grid-wide barrier (all blocks co-resident by construction) ----
    __threadfence();
    __syncthreads();
    if (threadIdx.x == 0) {
        atomicAdd(&g_arrive, 1);
        while (*(volatile int*)&g_arrive < (int)gridDim.x) { }
    }
    __syncthreads();

    // ---- phase 2: BN + ReLU on this block's nodes (rows are L2-hot) ----
    float invN = 1.0f / (float)N;
    float sc4[4], sh4[4];
#pragma unroll
    for (int q = 0; q < 4; q++) {
        int c = lane * 4 + q;
        float mean = g_colstats[c] * invN;
        float var  = g_colstats[D + c] * invN - mean * mean;
        float inv  = rsqrtf(var + 1e-5f);
        float scv  = gamma[c] * inv;
        sc4[q] = scv;
        sh4[q] = beta[c] - mean * scv;
    }

    for (int node = blockIdx.x * 8 + w; node < N; node += gridDim.x * 8) {
        float4 v = *(float4*)(out + (size_t)node * D + lane * 4);
        v.x = fmaxf(v.x * sc4[0] + sh4[0], 0.0f);
        v.y = fmaxf(v.y * sc4[1] + sh4[1], 0.0f);
        v.z = fmaxf(v.z * sc4[2] + sh4[2], 0.0f);
        v.w = fmaxf(v.w * sc4[3] + sh4[3], 0.0f);
        *(float4*)(out + (size_t)node * D + lane * 4) = v;
        if (lane == 0) g_cnt[node] = 0;          // self-clean for next call
    }
    if (blockIdx.x == 0 && threadIdx.x == 0) g_total = 0;
}

// ---------------------------------------------------------------------------
extern "C" void kernel_launch(void* const* d_in, const int* in_sizes, int n_in,
                              void* d_out, int out_size) {
    const float* x     = (const float*)d_in[0];
    const int*   pos   = (const int*)d_in[1];   // int32 (JAX canonicalizes int64)
    // d_in[2] = neg_edge_index: weight 0 => no-op, skipped
    const float* W     = (const float*)d_in[3];
    // d_in[4] = b: cancels exactly inside BatchNorm, skipped
    const float* gamma = (const float*)d_in[5];
    const float* beta  = (const float*)d_in[6];
    float*       out   = (float*)d_out;

    const int N  = in_sizes[0] / D;
    const int E  = in_sizes[1] / 2;
    const int GB = (N + 127) / 128;

    k_count <<<256, 256>>>(pos, E);
    k_alloc <<<(N + 255) / 256, 256>>>(N);
    kA      <<<GB + FB, 256>>>(x, W, pos, N, E, GB);
    k_gather<<<GATHER_BLOCKS, 256>>>(out, gamma, beta, N);
}